// round 4
// baseline (speedup 1.0000x reference)
#include <cuda_runtime.h>

#define NN 100000
#define NE 1600000
#define C  64

// ---- device scratch (no allocation allowed) ----
__device__ int   g_deg[NN];
__device__ int   g_off[NN];
__device__ int   g_cur[NN];
__device__ float g_dinv[NN];
__device__ int   g_srcs[NE];
__device__ float g_h1[(size_t)NN * C];
__device__ float g_h2[(size_t)NN * C];
__device__ float g_WlT[3][C * C];   // transposed: WlT[k*64+c] = Wl[c*64+k]
__device__ float g_WrT[3][C * C];

// ---------------- CSR build ----------------
__global__ void zero_deg_k() {
    int i = blockIdx.x * blockDim.x + threadIdx.x;
    if (i < NN) g_deg[i] = 0;
}

// edge_index is int32 on device (JAX default x64-disabled downcasts int64).
__global__ void count_k(const int* __restrict__ ei) {
    int e = blockIdx.x * blockDim.x + threadIdx.x;
    if (e < NE) {
        int dst = ei[NE + e];
        if ((unsigned)dst < (unsigned)NN) atomicAdd(&g_deg[dst], 1);
    }
}

// single-block exclusive scan over g_deg -> g_off, g_cur; also deg_inv
__global__ void scan_k() {
    __shared__ int wsum[32];
    __shared__ int carry;
    int tid  = threadIdx.x;
    int lane = tid & 31;
    int wid  = tid >> 5;
    if (tid == 0) carry = 0;
    __syncthreads();
    for (int base = 0; base < NN; base += 1024) {
        int i = base + tid;
        int v = (i < NN) ? g_deg[i] : 0;
        int x = v;
        #pragma unroll
        for (int o = 1; o < 32; o <<= 1) {
            int y = __shfl_up_sync(0xffffffffu, x, o);
            if (lane >= o) x += y;
        }
        if (lane == 31) wsum[wid] = x;
        __syncthreads();
        if (wid == 0) {
            int w = wsum[lane];
            #pragma unroll
            for (int o = 1; o < 32; o <<= 1) {
                int y = __shfl_up_sync(0xffffffffu, w, o);
                if (lane >= o) w += y;
            }
            wsum[lane] = w;
        }
        __syncthreads();
        int pre = (wid > 0) ? wsum[wid - 1] : 0;
        int c0  = carry;
        int excl = c0 + pre + x - v;
        if (i < NN) {
            g_off[i]  = excl;
            g_cur[i]  = excl;
            g_dinv[i] = 1.0f / (float)((v > 0) ? v : 1);
        }
        __syncthreads();
        if (tid == 0) carry = c0 + wsum[31];
        __syncthreads();
    }
}

__global__ void fill_k(const int* __restrict__ ei) {
    int e = blockIdx.x * blockDim.x + threadIdx.x;
    if (e < NE) {
        int src = ei[e];
        int dst = ei[NE + e];
        if ((unsigned)dst < (unsigned)NN && (unsigned)src < (unsigned)NN) {
            int p = atomicAdd(&g_cur[dst], 1);
            if ((unsigned)p < (unsigned)NE) g_srcs[p] = src;
        }
    }
}

// ---------------- weight transpose (once per launch, tiny) ----------------
__global__ void wtrans_k(const float* __restrict__ Wl0, const float* __restrict__ Wr0,
                         const float* __restrict__ Wl1, const float* __restrict__ Wr1,
                         const float* __restrict__ Wl2, const float* __restrict__ Wr2) {
    int l = blockIdx.x;  // 0..2
    const float* Wl = (l == 0) ? Wl0 : (l == 1) ? Wl1 : Wl2;
    const float* Wr = (l == 0) ? Wr0 : (l == 1) ? Wr1 : Wr2;
    for (int idx = threadIdx.x; idx < C * C; idx += blockDim.x) {
        int k = idx >> 6, c = idx & 63;
        g_WlT[l][idx] = Wl[c * C + k];   // write coalesced, read gathered (tiny)
        g_WrT[l][idx] = Wr[c * C + k];
    }
}

// ---------------- fused layer: mean-aggregate + dual-GEMM + bias (+relu) ----------------
// Block = 256 threads handles 32 nodes.
// Phase 1: 8 warps; warp w aggregates nodes w*4..w*4+3 (float2 per lane over 64 ch)
//          and stages h rows. Node-major smem [n][k], stride 64:
//          writes = consecutive float2 per node row (conflict-free),
//          GEMM reads = 16-thread broadcast x 2 banks (conflict-free). No padding.
// Phase 2: dual GEMM, 2 nodes x 4 channels register tile per thread.
// Static smem exactly 48KB.
__global__ void __launch_bounds__(256) layer_k(const float* __restrict__ x,
                                               const float* __restrict__ bl,
                                               float* __restrict__ outp,
                                               int layer, int insel, int outsel,
                                               int relu) {
    __shared__ float sWl[C * C];      // [k][c] 16KB
    __shared__ float sWr[C * C];      // [k][c] 16KB
    __shared__ float sA[32 * C];      // [n][k] 8KB (aggregated means)
    __shared__ float sH[32 * C];      // [n][k] 8KB (self features)

    const float* hin = (insel == 0) ? x : (insel == 1) ? g_h1 : g_h2;
    float* outb = (outsel == 1) ? g_h1 : (outsel == 2) ? g_h2 : outp;

    int tid = threadIdx.x;
    int v0  = blockIdx.x * 32;

    // stage transposed weights: coalesced, conflict-free
    const float* wlT = g_WlT[layer];
    const float* wrT = g_WrT[layer];
    #pragma unroll
    for (int it = 0; it < 16; it++) {
        int idx = it * 256 + tid;
        sWl[idx] = wlT[idx];
        sWr[idx] = wrT[idx];
    }

    // phase 1: aggregate 4 nodes per warp directly into smem
    int w = tid >> 5, l = tid & 31;
    #pragma unroll
    for (int j = 0; j < 4; j++) {
        int n = w * 4 + j;
        int v = v0 + n;
        float ax = 0.f, ay = 0.f;
        float2 hh = make_float2(0.f, 0.f);
        if (v < NN) {
            hh = ((const float2*)(hin + (size_t)v * C))[l];
            int s = g_off[v];
            int d = g_deg[v];
            int i = 0;
            for (; i + 4 <= d; i += 4) {
                int u0 = g_srcs[s + i + 0];
                int u1 = g_srcs[s + i + 1];
                int u2 = g_srcs[s + i + 2];
                int u3 = g_srcs[s + i + 3];
                float2 t0 = ((const float2*)(hin + (size_t)u0 * C))[l];
                float2 t1 = ((const float2*)(hin + (size_t)u1 * C))[l];
                float2 t2 = ((const float2*)(hin + (size_t)u2 * C))[l];
                float2 t3 = ((const float2*)(hin + (size_t)u3 * C))[l];
                ax += (t0.x + t1.x) + (t2.x + t3.x);
                ay += (t0.y + t1.y) + (t2.y + t3.y);
            }
            for (; i < d; i++) {
                int u = g_srcs[s + i];
                float2 t = ((const float2*)(hin + (size_t)u * C))[l];
                ax += t.x;
                ay += t.y;
            }
            float di = g_dinv[v];
            ax *= di;
            ay *= di;
        }
        *(float2*)(sA + n * C + 2 * l) = make_float2(ax, ay);
        *(float2*)(sH + n * C + 2 * l) = hh;
    }
    __syncthreads();

    // phase 2: dual GEMM
    int tc = tid & 15;    // channels tc*4 .. tc*4+3
    int tg = tid >> 4;    // node group: nodes tg*2, tg*2+1
    int n0 = tg * 2;

    float4 bias = ((const float4*)bl)[tc];
    float acc[2][4];
    #pragma unroll
    for (int j = 0; j < 2; j++) {
        acc[j][0] = bias.x; acc[j][1] = bias.y; acc[j][2] = bias.z; acc[j][3] = bias.w;
    }

    #pragma unroll 8
    for (int k = 0; k < C; k++) {
        float4 wl = *(const float4*)(sWl + k * C + tc * 4);
        float4 wr = *(const float4*)(sWr + k * C + tc * 4);
        float a0 = sA[n0 * C + k];
        float a1 = sA[(n0 + 1) * C + k];
        float h0 = sH[n0 * C + k];
        float h1 = sH[(n0 + 1) * C + k];
        acc[0][0] += a0 * wl.x + h0 * wr.x;
        acc[0][1] += a0 * wl.y + h0 * wr.y;
        acc[0][2] += a0 * wl.z + h0 * wr.z;
        acc[0][3] += a0 * wl.w + h0 * wr.w;
        acc[1][0] += a1 * wl.x + h1 * wr.x;
        acc[1][1] += a1 * wl.y + h1 * wr.y;
        acc[1][2] += a1 * wl.z + h1 * wr.z;
        acc[1][3] += a1 * wl.w + h1 * wr.w;
    }

    #pragma unroll
    for (int j = 0; j < 2; j++) {
        int v = v0 + n0 + j;
        if (v < NN) {
            float4 r;
            r.x = acc[j][0]; r.y = acc[j][1]; r.z = acc[j][2]; r.w = acc[j][3];
            if (relu) {
                r.x = fmaxf(r.x, 0.f); r.y = fmaxf(r.y, 0.f);
                r.z = fmaxf(r.z, 0.f); r.w = fmaxf(r.w, 0.f);
            }
            *(float4*)(outb + (size_t)v * C + tc * 4) = r;
        }
    }
}

extern "C" void kernel_launch(void* const* d_in, const int* in_sizes, int n_in,
                              void* d_out, int out_size) {
    const float* x   = (const float*)d_in[0];
    const int*   ei  = (const int*)d_in[1];    // int32 (JAX x64-disabled)
    const float* Wl0 = (const float*)d_in[2];
    const float* bl0 = (const float*)d_in[3];
    const float* Wr0 = (const float*)d_in[4];
    const float* Wl1 = (const float*)d_in[5];
    const float* bl1 = (const float*)d_in[6];
    const float* Wr1 = (const float*)d_in[7];
    const float* Wl2 = (const float*)d_in[8];
    const float* bl2 = (const float*)d_in[9];
    const float* Wr2 = (const float*)d_in[10];
    float* out = (float*)d_out;

    // CSR build + weight transpose
    zero_deg_k<<<(NN + 255) / 256, 256>>>();
    count_k<<<(NE + 255) / 256, 256>>>(ei);
    scan_k<<<1, 1024>>>();
    fill_k<<<(NE + 255) / 256, 256>>>(ei);
    wtrans_k<<<3, 256>>>(Wl0, Wr0, Wl1, Wr1, Wl2, Wr2);

    const int LB = (NN + 31) / 32;  // 32 nodes per block

    layer_k<<<LB, 256>>>(x, bl0, out, 0, 0, 1, 1);  // x    -> g_h1 (relu)
    layer_k<<<LB, 256>>>(x, bl1, out, 1, 1, 2, 1);  // g_h1 -> g_h2 (relu)
    layer_k<<<LB, 256>>>(x, bl2, out, 2, 2, 0, 0);  // g_h2 -> out
}

// round 5
// speedup vs baseline: 2.3204x; 2.3204x over previous
#include <cuda_runtime.h>
#include <cstdint>

#define NN 100000
#define NE 1600000
#define C  64
#define NBLK 98           // ceil(100000/1024)

// ---- device scratch (no allocation allowed) ----
__device__ int   g_deg[NN];
__device__ int   g_off[NN];
__device__ int   g_cur[NN];
__device__ float g_dinv[NN];
__device__ int   g_srcs[NE];
__device__ float g_h1[(size_t)NN * C];
__device__ float g_h2[(size_t)NN * C];
__device__ float g_agg[(size_t)NN * C];
__device__ float g_Whi[3][2][C * C];   // [layer][0=Wl,1=Wr] transposed k-major, tf32-hi part
__device__ float g_Wlo[3][2][C * C];   // tf32-lo part
__device__ int   g_bsum[128];
__device__ int   g_boff[128];

// ---------------- helpers ----------------
__device__ __forceinline__ uint32_t f2tf(float v) {
    uint32_t r;
    asm("cvt.rna.tf32.f32 %0, %1;" : "=r"(r) : "f"(v));
    return r;
}

__device__ __forceinline__ void mma8(float* c, uint32_t a0, uint32_t a1, uint32_t a2, uint32_t a3,
                                     uint32_t b0, uint32_t b1) {
    asm volatile("mma.sync.aligned.m16n8k8.row.col.f32.tf32.tf32.f32 "
                 "{%0,%1,%2,%3}, {%4,%5,%6,%7}, {%8,%9}, {%0,%1,%2,%3};"
                 : "+f"(c[0]), "+f"(c[1]), "+f"(c[2]), "+f"(c[3])
                 : "r"(a0), "r"(a1), "r"(a2), "r"(a3), "r"(b0), "r"(b1));
}

// ---------------- CSR build ----------------
__global__ void zero_deg_k() {
    int i = blockIdx.x * blockDim.x + threadIdx.x;
    if (i < NN) g_deg[i] = 0;
}

// edge_index is int32 on device (JAX default x64-disabled downcasts int64).
__global__ void count_k(const int* __restrict__ ei) {
    int e = blockIdx.x * blockDim.x + threadIdx.x;
    if (e < NE) {
        int dst = ei[NE + e];
        if ((unsigned)dst < (unsigned)NN) atomicAdd(&g_deg[dst], 1);
    }
}

// two-level scan: block sums
__global__ void bsum_k() {
    __shared__ int ws[32];
    int t = threadIdx.x, b = blockIdx.x;
    int i = b * 1024 + t;
    int v = (i < NN) ? g_deg[i] : 0;
    #pragma unroll
    for (int o = 16; o > 0; o >>= 1) v += __shfl_down_sync(0xffffffffu, v, o);
    if ((t & 31) == 0) ws[t >> 5] = v;
    __syncthreads();
    if (t < 32) {
        int s = ws[t];
        #pragma unroll
        for (int o = 16; o > 0; o >>= 1) s += __shfl_down_sync(0xffffffffu, s, o);
        if (t == 0) g_bsum[b] = s;
    }
}

// scan the 98 block sums (1 block of 128)
__global__ void bscan_k() {
    __shared__ int ws[4];
    int t = threadIdx.x, lane = t & 31, w = t >> 5;
    int v = (t < NBLK) ? g_bsum[t] : 0;
    int x = v;
    #pragma unroll
    for (int o = 1; o < 32; o <<= 1) {
        int y = __shfl_up_sync(0xffffffffu, x, o);
        if (lane >= o) x += y;
    }
    if (lane == 31) ws[w] = x;
    __syncthreads();
    int pre = 0;
    if (w > 0) {
        #pragma unroll
        for (int j = 0; j < 3; j++) if (j < w) pre += ws[j];
    }
    if (t < NBLK) g_boff[t] = pre + x - v;   // exclusive
}

// per-tile rescan + add block offset; write off/cur/dinv
__global__ void scatter_scan_k() {
    __shared__ int wsum[32];
    int t = threadIdx.x, b = blockIdx.x;
    int lane = t & 31, w = t >> 5;
    int i = b * 1024 + t;
    int v = (i < NN) ? g_deg[i] : 0;
    int x = v;
    #pragma unroll
    for (int o = 1; o < 32; o <<= 1) {
        int y = __shfl_up_sync(0xffffffffu, x, o);
        if (lane >= o) x += y;
    }
    if (lane == 31) wsum[w] = x;
    __syncthreads();
    if (w == 0) {
        int s = wsum[lane];
        #pragma unroll
        for (int o = 1; o < 32; o <<= 1) {
            int y = __shfl_up_sync(0xffffffffu, s, o);
            if (lane >= o) s += y;
        }
        wsum[lane] = s;
    }
    __syncthreads();
    int pre = (w > 0) ? wsum[w - 1] : 0;
    if (i < NN) {
        int excl = g_boff[b] + pre + x - v;
        g_off[i]  = excl;
        g_cur[i]  = excl;
        g_dinv[i] = 1.0f / (float)((v > 0) ? v : 1);
    }
}

__global__ void fill_k(const int* __restrict__ ei) {
    int e = blockIdx.x * blockDim.x + threadIdx.x;
    if (e < NE) {
        int src = ei[e];
        int dst = ei[NE + e];
        if ((unsigned)dst < (unsigned)NN && (unsigned)src < (unsigned)NN) {
            int p = atomicAdd(&g_cur[dst], 1);
            if ((unsigned)p < (unsigned)NE) g_srcs[p] = src;
        }
    }
}

// ---------------- weight transpose + tf32 hi/lo split (once, tiny) ----------------
__global__ void wtrans_k(const float* __restrict__ Wl0, const float* __restrict__ Wr0,
                         const float* __restrict__ Wl1, const float* __restrict__ Wr1,
                         const float* __restrict__ Wl2, const float* __restrict__ Wr2) {
    int l = blockIdx.x;  // 0..2
    const float* Wl = (l == 0) ? Wl0 : (l == 1) ? Wl1 : Wl2;
    const float* Wr = (l == 0) ? Wr0 : (l == 1) ? Wr1 : Wr2;
    for (int idx = threadIdx.x; idx < C * C; idx += blockDim.x) {
        int k = idx >> 6, c = idx & 63;
        float vl = Wl[c * C + k];
        float vr = Wr[c * C + k];
        uint32_t hl = f2tf(vl);
        uint32_t hr = f2tf(vr);
        float hlf = __uint_as_float(hl);
        float hrf = __uint_as_float(hr);
        g_Whi[l][0][idx] = hlf;
        g_Wlo[l][0][idx] = __uint_as_float(f2tf(vl - hlf));
        g_Whi[l][1][idx] = hrf;
        g_Wlo[l][1][idx] = __uint_as_float(f2tf(vr - hrf));
    }
}

// ---------------- mean aggregation: warp per node (r3-proven) ----------------
__global__ void __launch_bounds__(256) agg_k(const float* __restrict__ x, int insel) {
    const float* in = (insel == 0) ? x : (insel == 1) ? g_h1 : g_h2;
    int warp = (blockIdx.x * blockDim.x + threadIdx.x) >> 5;
    int lane = threadIdx.x & 31;
    if (warp >= NN) return;
    int s = g_off[warp];
    int d = g_deg[warp];
    float ax = 0.f, ay = 0.f;
    int i = 0;
    for (; i + 4 <= d; i += 4) {
        int u0 = g_srcs[s + i + 0];
        int u1 = g_srcs[s + i + 1];
        int u2 = g_srcs[s + i + 2];
        int u3 = g_srcs[s + i + 3];
        float2 t0 = ((const float2*)(in + (size_t)u0 * C))[lane];
        float2 t1 = ((const float2*)(in + (size_t)u1 * C))[lane];
        float2 t2 = ((const float2*)(in + (size_t)u2 * C))[lane];
        float2 t3 = ((const float2*)(in + (size_t)u3 * C))[lane];
        ax += (t0.x + t1.x) + (t2.x + t3.x);
        ay += (t0.y + t1.y) + (t2.y + t3.y);
    }
    for (; i < d; i++) {
        int u = g_srcs[s + i];
        float2 t = ((const float2*)(in + (size_t)u * C))[lane];
        ax += t.x;
        ay += t.y;
    }
    float di = g_dinv[warp];
    ((float2*)(g_agg + (size_t)warp * C))[lane] = make_float2(ax * di, ay * di);
}

// ---------------- tensor-core transform: 3xTF32 dual GEMM ----------------
// out[v][c] = sum_k agg[v][k]*WlT[k][c] + bl[c] + sum_k h[v][k]*WrT[k][c] (+relu)
// Block = 64 nodes x 64 channels, 256 threads (8 warps).
// Warp (mg=wid>>2, ng=wid&3): m-tiles mt in {0,1} (16 rows each), n-tiles nt in {0,1} (8 cols).
// Strides: weights k-major stride 72 (bank = 8*tig+gid, conflict-free);
//          A/H node-major stride 68 (bank = 4*gid+tig, conflict-free).
#define WS 72
#define AS 68
__global__ void __launch_bounds__(256) xform_k(const float* __restrict__ x,
                                               const float* __restrict__ bl,
                                               float* __restrict__ outp,
                                               int layer, int insel, int outsel,
                                               int relu) {
    extern __shared__ float sm[];
    float* sWlHi = sm;                       // [64][WS]
    float* sWlLo = sWlHi + C * WS;
    float* sWrHi = sWlLo + C * WS;
    float* sWrLo = sWrHi + C * WS;
    float* sA    = sWrLo + C * WS;           // [64][AS]
    float* sH    = sA + 64 * AS;

    const float* hin = (insel == 0) ? x : (insel == 1) ? g_h1 : g_h2;
    float* outb = (outsel == 1) ? g_h1 : (outsel == 2) ? g_h2 : outp;

    int tid = threadIdx.x;
    int v0  = blockIdx.x * 64;

    // stage weights (coalesced reads; STS bank = 8k + c, conflict-free)
    const float* whl = g_Whi[layer][0];
    const float* wll = g_Wlo[layer][0];
    const float* whr = g_Whi[layer][1];
    const float* wlr = g_Wlo[layer][1];
    #pragma unroll
    for (int it = 0; it < 16; it++) {
        int i = it * 256 + tid;
        int k = i >> 6, c = i & 63;
        int p = k * WS + c;
        sWlHi[p] = whl[i];
        sWlLo[p] = wll[i];
        sWrHi[p] = whr[i];
        sWrLo[p] = wlr[i];
    }
    // stage A/H (64 rows x 16 float4; 2 rows per warp -> coalesced)
    #pragma unroll
    for (int it = 0; it < 4; it++) {
        int i = it * 256 + tid;        // 0..1023
        int n = i >> 4, q = i & 15;
        int v = v0 + n;
        float4 a = make_float4(0.f, 0.f, 0.f, 0.f), h = a;
        if (v < NN) {
            a = ((const float4*)(g_agg + (size_t)v * C))[q];
            h = ((const float4*)(hin   + (size_t)v * C))[q];
        }
        int base = n * AS + q * 4;
        sA[base + 0] = a.x; sA[base + 1] = a.y; sA[base + 2] = a.z; sA[base + 3] = a.w;
        sH[base + 0] = h.x; sH[base + 1] = h.y; sH[base + 2] = h.z; sH[base + 3] = h.w;
    }
    __syncthreads();

    int lane = tid & 31, gid = lane >> 2, tig = lane & 3;
    int wid = tid >> 5, mg = wid >> 2, ng = wid & 3;

    // accumulators init with bias
    float acc[2][2][4];
    #pragma unroll
    for (int nt = 0; nt < 2; nt++) {
        int col = ng * 16 + nt * 8 + 2 * tig;
        float b0 = bl[col], b1 = bl[col + 1];
        #pragma unroll
        for (int mt = 0; mt < 2; mt++) {
            acc[mt][nt][0] = b0; acc[mt][nt][1] = b1;
            acc[mt][nt][2] = b0; acc[mt][nt][3] = b1;
        }
    }

    for (int ks = 0; ks < 8; ks++) {
        int k0 = ks * 8;
        // B fragments (k-major, col-major frag: b0=(k0+tig, n), b1=(k0+tig+4, n))
        uint32_t blh[2][2], bll[2][2], brh[2][2], brl[2][2];
        #pragma unroll
        for (int nt = 0; nt < 2; nt++) {
            int n = ng * 16 + nt * 8 + gid;
            int p0 = (k0 + tig) * WS + n;
            int p1 = (k0 + tig + 4) * WS + n;
            blh[nt][0] = __float_as_uint(sWlHi[p0]); blh[nt][1] = __float_as_uint(sWlHi[p1]);
            bll[nt][0] = __float_as_uint(sWlLo[p0]); bll[nt][1] = __float_as_uint(sWlLo[p1]);
            brh[nt][0] = __float_as_uint(sWrHi[p0]); brh[nt][1] = __float_as_uint(sWrHi[p1]);
            brl[nt][0] = __float_as_uint(sWrLo[p0]); brl[nt][1] = __float_as_uint(sWrLo[p1]);
        }
        #pragma unroll
        for (int mt = 0; mt < 2; mt++) {
            int r = mg * 32 + mt * 16 + gid;   // local row
            int pa = r * AS + k0 + tig;
            int pb = (r + 8) * AS + k0 + tig;
            float a0f = sA[pa], a1f = sA[pb], a2f = sA[pa + 4], a3f = sA[pb + 4];
            float h0f = sH[pa], h1f = sH[pb], h2f = sH[pa + 4], h3f = sH[pb + 4];
            uint32_t ah0 = f2tf(a0f), ah1 = f2tf(a1f), ah2 = f2tf(a2f), ah3 = f2tf(a3f);
            uint32_t al0 = f2tf(a0f - __uint_as_float(ah0));
            uint32_t al1 = f2tf(a1f - __uint_as_float(ah1));
            uint32_t al2 = f2tf(a2f - __uint_as_float(ah2));
            uint32_t al3 = f2tf(a3f - __uint_as_float(ah3));
            uint32_t hh0 = f2tf(h0f), hh1 = f2tf(h1f), hh2 = f2tf(h2f), hh3 = f2tf(h3f);
            uint32_t hl0 = f2tf(h0f - __uint_as_float(hh0));
            uint32_t hl1 = f2tf(h1f - __uint_as_float(hh1));
            uint32_t hl2 = f2tf(h2f - __uint_as_float(hh2));
            uint32_t hl3 = f2tf(h3f - __uint_as_float(hh3));
            #pragma unroll
            for (int nt = 0; nt < 2; nt++) {
                float* cc = acc[mt][nt];
                mma8(cc, ah0, ah1, ah2, ah3, blh[nt][0], blh[nt][1]);  // hi*hi
                mma8(cc, al0, al1, al2, al3, blh[nt][0], blh[nt][1]);  // lo*hi
                mma8(cc, ah0, ah1, ah2, ah3, bll[nt][0], bll[nt][1]);  // hi*lo
                mma8(cc, hh0, hh1, hh2, hh3, brh[nt][0], brh[nt][1]);
                mma8(cc, hl0, hl1, hl2, hl3, brh[nt][0], brh[nt][1]);
                mma8(cc, hh0, hh1, hh2, hh3, brl[nt][0], brl[nt][1]);
            }
        }
    }

    // store: c0=(row, col), c1=(row, col+1), c2=(row+8, col), c3=(row+8, col+1)
    #pragma unroll
    for (int mt = 0; mt < 2; mt++) {
        int row = v0 + mg * 32 + mt * 16 + gid;
        #pragma unroll
        for (int nt = 0; nt < 2; nt++) {
            int col = ng * 16 + nt * 8 + 2 * tig;
            float2 r0 = make_float2(acc[mt][nt][0], acc[mt][nt][1]);
            float2 r1 = make_float2(acc[mt][nt][2], acc[mt][nt][3]);
            if (relu) {
                r0.x = fmaxf(r0.x, 0.f); r0.y = fmaxf(r0.y, 0.f);
                r1.x = fmaxf(r1.x, 0.f); r1.y = fmaxf(r1.y, 0.f);
            }
            if (row < NN)     *(float2*)(outb + (size_t)row * C + col)       = r0;
            if (row + 8 < NN) *(float2*)(outb + (size_t)(row + 8) * C + col) = r1;
        }
    }
}

extern "C" void kernel_launch(void* const* d_in, const int* in_sizes, int n_in,
                              void* d_out, int out_size) {
    const float* x   = (const float*)d_in[0];
    const int*   ei  = (const int*)d_in[1];    // int32 (JAX x64-disabled)
    const float* Wl0 = (const float*)d_in[2];
    const float* bl0 = (const float*)d_in[3];
    const float* Wr0 = (const float*)d_in[4];
    const float* Wl1 = (const float*)d_in[5];
    const float* bl1 = (const float*)d_in[6];
    const float* Wr1 = (const float*)d_in[7];
    const float* Wl2 = (const float*)d_in[8];
    const float* bl2 = (const float*)d_in[9];
    const float* Wr2 = (const float*)d_in[10];
    float* out = (float*)d_out;

    const int XSMEM = (4 * C * WS + 2 * 64 * AS) * (int)sizeof(float);  // 108544 B
    static int configured = 0;
    cudaFuncSetAttribute(xform_k, cudaFuncAttributeMaxDynamicSharedMemorySize, XSMEM);
    (void)configured;

    // CSR build + weight prep
    zero_deg_k<<<(NN + 255) / 256, 256>>>();
    count_k<<<(NE + 255) / 256, 256>>>(ei);
    bsum_k<<<NBLK, 1024>>>();
    bscan_k<<<1, 128>>>();
    scatter_scan_k<<<NBLK, 1024>>>();
    fill_k<<<(NE + 255) / 256, 256>>>(ei);
    wtrans_k<<<3, 256>>>(Wl0, Wr0, Wl1, Wr1, Wl2, Wr2);

    const int AGG_BLOCKS = (NN + 7) / 8;     // 8 warps (nodes) per 256-thread block
    const int XF_BLOCKS  = (NN + 63) / 64;   // 64 nodes per block

    agg_k<<<AGG_BLOCKS, 256>>>(x, 0);
    xform_k<<<XF_BLOCKS, 256, XSMEM>>>(x, bl0, out, 0, 0, 1, 1);  // x    -> g_h1 (relu)
    agg_k<<<AGG_BLOCKS, 256>>>(x, 1);
    xform_k<<<XF_BLOCKS, 256, XSMEM>>>(x, bl1, out, 1, 1, 2, 1);  // g_h1 -> g_h2 (relu)
    agg_k<<<AGG_BLOCKS, 256>>>(x, 2);
    xform_k<<<XF_BLOCKS, 256, XSMEM>>>(x, bl2, out, 2, 2, 0, 0);  // g_h2 -> out
}